// round 14
// baseline (speedup 1.0000x reference)
#include <cuda_runtime.h>
#include <cuda_bf16.h>
#include <cstdint>

#define BB 2
#define NN 2048
#define DIN 256
#define HH 8
#define DH 32
#define BH (BB*HH)            // 16
#define NWORDS (NN/32)        // 64
#define SCALEF 0.17677669529663688f   // 1/sqrt(32)
#define NTILES (NN/64)        // 32

typedef unsigned long long ull;
typedef uint32_t u32;

// ---------------- scratch ----------------------------------------------------
__device__ unsigned      g_bits[BB*NN*NWORDS];
__device__ __nv_bfloat16 g_Qb[BH*NN*64];    // [bh][n][hi32|lo32], prescaled
__device__ __nv_bfloat16 g_Kb[BH*NN*64];    // [bh][n][hi32|lo32]
__device__ __nv_bfloat16 g_Vtb[BH*64*NN];   // [bh][d<32 Vh^T | d>=32 Vl^T][n]
__device__ __nv_bfloat16 g_xb[4096*512];    // [row][hi256|lo256]
__device__ __nv_bfloat16 g_Wb[4*256*512];   // [w][n][hi256|lo256]  w: q,k,v,o
__device__ __nv_bfloat16 g_attnb[4096*512]; // [row][hi256|lo256]

#define SWZ(o) ((o) ^ (((o) >> 3) & 0x70))

// mma.sync m16n8k16 bf16 -> f32 accumulate (portable, sm_80+ PTX)
#define MMA16816(d, a, B0, B1) asm volatile( \
    "mma.sync.aligned.m16n8k16.row.col.f32.bf16.bf16.f32 " \
    "{%0,%1,%2,%3},{%4,%5,%6,%7},{%8,%9},{%0,%1,%2,%3};" \
    : "+f"((d)[0]), "+f"((d)[1]), "+f"((d)[2]), "+f"((d)[3]) \
    : "r"((a)[0]), "r"((a)[1]), "r"((a)[2]), "r"((a)[3]), "r"(B0), "r"(B1))

__device__ __forceinline__ u32 bf16x2_of(float hi, float lo) {
    u32 r; asm("cvt.rn.bf16x2.f32 %0, %1, %2;" : "=r"(r) : "f"(hi), "f"(lo));
    return r;   // upper half = hi arg, lower half = lo arg
}

__device__ __forceinline__ u32 smem_to_u32(const void* p) {
    u32 a;
    asm("{ .reg .u64 t; cvta.to.shared.u64 t, %1; cvt.u32.u64 %0, t; }" : "=r"(a) : "l"(p));
    return a;
}
#define CP16(dst_u32, src_ptr) asm volatile( \
    "cp.async.cg.shared.global [%0], [%1], 16;" :: "r"(dst_u32), "l"(src_ptr))
#define CP8(dst_u32, src_ptr) asm volatile( \
    "cp.async.ca.shared.global [%0], [%1], 8;" :: "r"(dst_u32), "l"(src_ptr))
#define CP_COMMIT() asm volatile("cp.async.commit_group;" ::: "memory")
#define CP_WAIT0()  asm volatile("cp.async.wait_group 0;" ::: "memory")

// ---------------- adjacency -> bitmask ---------------------------------------
__global__ __launch_bounds__(256) void adjbits_kernel(const float* __restrict__ adj) {
    int w = blockIdx.x * 256 + threadIdx.x;
    const float4* a = (const float4*)(adj + (size_t)w * 32);
    unsigned m = 0;
#pragma unroll
    for (int t = 0; t < 8; t++) {
        float4 v = a[t];
        m |= (v.x != 0.f ? 1u : 0u) << (4 * t + 0);
        m |= (v.y != 0.f ? 1u : 0u) << (4 * t + 1);
        m |= (v.z != 0.f ? 1u : 0u) << (4 * t + 2);
        m |= (v.w != 0.f ? 1u : 0u) << (4 * t + 3);
    }
    g_bits[w] = m;
}

// ---------------- split fp32 -> bf16 hi/lo ------------------------------------
__device__ __forceinline__ void split4(float4 v, u32& hA, u32& hB, u32& lA, u32& lB) {
    hA = bf16x2_of(v.y, v.x);
    hB = bf16x2_of(v.w, v.z);
    float r0 = __uint_as_float(hA << 16), r1 = __uint_as_float(hA & 0xffff0000u);
    float r2 = __uint_as_float(hB << 16), r3 = __uint_as_float(hB & 0xffff0000u);
    lA = bf16x2_of(v.y - r1, v.x - r0);
    lB = bf16x2_of(v.w - r3, v.z - r2);
}

__global__ __launch_bounds__(256) void split_x(const float* __restrict__ src) {
    int idx = blockIdx.x * 256 + threadIdx.x;      // quads over 4096*64
    float4 v = ((const float4*)src)[idx];
    int row = idx >> 6, c4 = (idx & 63) * 4;
    u32 hA, hB, lA, lB; split4(v, hA, hB, lA, lB);
    *(uint2*)(g_xb + (size_t)row * 512 + c4)       = make_uint2(hA, hB);
    *(uint2*)(g_xb + (size_t)row * 512 + 256 + c4) = make_uint2(lA, lB);
}

__global__ __launch_bounds__(256) void split_w(const float* __restrict__ Wq,
                                               const float* __restrict__ Wk,
                                               const float* __restrict__ Wv,
                                               const float* __restrict__ Wo) {
    int idx = blockIdx.x * 256 + threadIdx.x;      // quads over 4*256*64
    int w = idx >> 14;
    const float* src = (w == 0) ? Wq : (w == 1) ? Wk : (w == 2) ? Wv : Wo;
    int li = idx & 16383;
    float4 v = ((const float4*)src)[li];
    int row = li >> 6, c4 = (li & 63) * 4;
    u32 hA, hB, lA, lB; split4(v, hA, hB, lA, lB);
    __nv_bfloat16* d = g_Wb + ((size_t)w * 256 + row) * 512;
    *(uint2*)(d + c4)       = make_uint2(hA, hB);
    *(uint2*)(d + 256 + c4) = make_uint2(lA, lB);
}

// ---------------- HMMA GEMM: C(4096x256) = A(4096x256) @ W^T -----------------
// A, W split bf16 (hi|lo, 512 wide). K=768 in 12 chunks of 64:
//   p0: Ah.Wh  p1: Al.Wh  p2: Ah.Wl   (drop Al.Wl ~ 2^-16)
// cp.async double-buffered; tile 128m x 64n, 8 warps, warp owns 16 m-rows.
#define GS_A 0
#define GS_B 16384
#define GS_TILE 24576

template <int MODE>
__global__ __launch_bounds__(256) void hgemm(const __nv_bfloat16* __restrict__ A,
                                             const float* __restrict__ bias,
                                             float* __restrict__ out) {
    __shared__ __align__(1024) char sm[2 * GS_TILE];
    const u32 smb = smem_to_u32(sm);
    const int tid = threadIdx.x;
    const int wid = tid >> 5, lane = tid & 31;
    const int g = lane >> 2, tig = lane & 3;
    const int m0 = blockIdx.x * 128;
    const int n0 = blockIdx.y * 64;
    const int z = (MODE == 1) ? blockIdx.z : 3;
    const __nv_bfloat16* W = g_Wb + (size_t)z * 256 * 512;
    const float scale = (MODE == 1 && z == 0) ? SCALEF : 1.0f;

    auto stage = [&](int c) {
        const int p = c >> 2, k0 = (c & 3) * 64;
        const int aCol = ((p == 1) ? 256 : 0) + k0;
        const int bCol = ((p == 2) ? 256 : 0) + k0;
        const u32 dst = smb + ((c & 1) ? GS_TILE : 0);
        const char* ag = (const char*)(A + (size_t)m0 * 512 + aCol);
#pragma unroll
        for (int i = 0; i < 4; i++) {
            int off = (tid + 256 * i) * 16;
            int row = off >> 7, wi = off & 127;
            CP16(dst + GS_A + SWZ(off), ag + (size_t)row * 1024 + wi);
        }
        const char* bg = (const char*)(W + (size_t)n0 * 512 + bCol);
#pragma unroll
        for (int i = 0; i < 2; i++) {
            int off = (tid + 256 * i) * 16;
            int row = off >> 7, wi = off & 127;
            CP16(dst + GS_B + SWZ(off), bg + (size_t)row * 1024 + wi);
        }
        CP_COMMIT();
    };

    float o[8][4];
#pragma unroll
    for (int tt = 0; tt < 8; tt++)
#pragma unroll
        for (int c = 0; c < 4; c++) o[tt][c] = 0.f;

    stage(0);
#pragma unroll 1
    for (int c = 0; c < 12; c++) {
        CP_WAIT0();
        __syncthreads();
        if (c + 1 < 12) stage(c + 1);
        const char* sp = sm + ((c & 1) ? GS_TILE : 0);

        u32 a[4][4];
#pragma unroll
        for (int ks = 0; ks < 4; ks++)
#pragma unroll
            for (int r = 0; r < 4; r++) {
                int row = wid * 16 + g + 8 * (r & 1);
                int kb = 4 * tig + 32 * ks + ((r >= 2) ? 16 : 0);
                a[ks][r] = *(const u32*)(sp + GS_A + SWZ(row * 128 + kb));
            }

#pragma unroll
        for (int ks = 0; ks < 4; ks++) {
            u32 b0[8], b1[8];
#pragma unroll
            for (int tt = 0; tt < 8; tt++) {
                int j = 8 * tt + g;
                int kb = 4 * tig + 32 * ks;
                b0[tt] = *(const u32*)(sp + GS_B + SWZ(j * 128 + kb));
                b1[tt] = *(const u32*)(sp + GS_B + SWZ(j * 128 + kb + 16));
            }
#pragma unroll
            for (int tt = 0; tt < 8; tt++)
                MMA16816(o[tt], a[ks], b0[tt], b1[tt]);
        }
        __syncthreads();
    }

    // ---- epilogue ----
    if (MODE == 0) {
#pragma unroll
        for (int tt = 0; tt < 8; tt++) {
            int rA = m0 + wid * 16 + g;
            int cA = n0 + 8 * tt + 2 * tig;
            float2 bi = *(const float2*)(bias + cA);
            *(float2*)(out + (size_t)rA * 256 + cA) =
                make_float2(o[tt][0] + bi.x, o[tt][1] + bi.y);
            *(float2*)(out + (size_t)(rA + 8) * 256 + cA) =
                make_float2(o[tt][2] + bi.x, o[tt][3] + bi.y);
        }
    } else {
#pragma unroll
        for (int tt = 0; tt < 8; tt++) {
            int cA = n0 + 8 * tt + 2 * tig;            // even
            int h = cA >> 5, d = cA & 31;
#pragma unroll
            for (int half = 0; half < 2; half++) {
                int row = m0 + wid * 16 + g + 8 * half;
                int b_ = row >> 11, n = row & (NN - 1);
                int bh = b_ * HH + h;
                float v0 = o[tt][2 * half] * scale;
                float v1 = o[tt][2 * half + 1] * scale;
                u32 hp = bf16x2_of(v1, v0);
                float r0 = __uint_as_float(hp << 16);
                float r1 = __uint_as_float(hp & 0xffff0000u);
                u32 lp = bf16x2_of(v1 - r1, v0 - r0);
                if (z < 2) {
                    __nv_bfloat16* dst = (z == 0 ? g_Qb : g_Kb) + ((size_t)bh * NN + n) * 64;
                    *(u32*)(dst + d) = hp;
                    *(u32*)(dst + 32 + d) = lp;
                } else {
                    __nv_bfloat16 h0 = __float2bfloat16(v0);
                    __nv_bfloat16 h1 = __float2bfloat16(v1);
                    __nv_bfloat16 l0 = __float2bfloat16(v0 - __bfloat162float(h0));
                    __nv_bfloat16 l1 = __float2bfloat16(v1 - __bfloat162float(h1));
                    __nv_bfloat16* vb = g_Vtb + (size_t)bh * 64 * NN + n;
                    vb[(size_t)d * NN] = h0;
                    vb[(size_t)(d + 1) * NN] = h1;
                    vb[(size_t)(d + 32) * NN] = l0;
                    vb[(size_t)(d + 33) * NN] = l1;
                }
            }
        }
    }
}

// ---------------- HMMA flash attention (cp.async double-buffered) -------------
// grid (16 q-tiles, 16 bh), 256 threads = 8 warps. Warp w owns q rows [16w,16w+16).
#define SM_KB 0
#define SM_VB 8192
#define SM_MB 16384
#define SM_TILE 17408

__global__ __launch_bounds__(256) void attn_kernel() {
    __shared__ __align__(1024) char sm[2 * SM_TILE];
    const u32 smb = smem_to_u32(sm);
    const int tid = threadIdx.x;
    const int wid = tid >> 5, lane = tid & 31;
    const int g = lane >> 2, tig = lane & 3;
    const int bh = blockIdx.y, b = bh >> 3;
    const int n0 = blockIdx.x * 128;

    auto stage = [&](int t) {
        const u32 dst = smb + ((t & 1) ? SM_TILE : 0);
        const char* kg = (const char*)g_Kb + ((size_t)(bh * NN + t * 64)) * 128;
#pragma unroll
        for (int i = 0; i < 2; i++) {
            int off = (tid + 256 * i) * 16;
            CP16(dst + SM_KB + SWZ(off), kg + off);
        }
        const char* vg = (const char*)g_Vtb + (size_t)bh * 64 * (NN * 2) + t * 128;
#pragma unroll
        for (int i = 0; i < 2; i++) {
            int cc = tid + 256 * i;
            int d = cc >> 3, u = cc & 7;
            CP16(dst + SM_VB + SWZ(cc * 16), vg + (size_t)d * (NN * 2) + u * 16);
        }
        if (tid < 128)
            CP8(dst + SM_MB + tid * 8,
                (const char*)(g_bits + ((size_t)(b * NN + n0 + tid)) * NWORDS + t * 2));
        CP_COMMIT();
    };

    u32 aQ[4][4];
    {
        const char* qg = (const char*)g_Qb + ((size_t)(bh * NN + n0 + wid * 16)) * 128;
#pragma unroll
        for (int ks = 0; ks < 4; ks++)
#pragma unroll
            for (int r = 0; r < 4; r++) {
                int row = g + 8 * (r & 1);
                int kb = 4 * tig + 32 * ks + ((r >= 2) ? 16 : 0);
                aQ[ks][r] = *(const u32*)(qg + row * 128 + kb);
            }
    }

    float o[4][4];
#pragma unroll
    for (int tn = 0; tn < 4; tn++)
#pragma unroll
        for (int c = 0; c < 4; c++) o[tn][c] = 0.f;
    float lsum[2] = {0.f, 0.f};

    stage(0);
#pragma unroll 1
    for (int t = 0; t < NTILES; t++) {
        CP_WAIT0();
        __syncthreads();
        if (t + 1 < NTILES) stage(t + 1);
        const char* sp = sm + ((t & 1) ? SM_TILE : 0);

        float cf[8][4];
#pragma unroll
        for (int tt = 0; tt < 8; tt++)
#pragma unroll
            for (int c = 0; c < 4; c++) cf[tt][c] = 0.f;

#pragma unroll
        for (int ks = 0; ks < 4; ks++) {
            u32 b0[8], b1[8];
#pragma unroll
            for (int tt = 0; tt < 8; tt++) {
                int j = 8 * tt + g;
                int kb = 4 * tig + 32 * ks;
                b0[tt] = *(const u32*)(sp + SM_KB + SWZ(j * 128 + kb));
                b1[tt] = *(const u32*)(sp + SM_KB + SWZ(j * 128 + kb + 16));
            }
#pragma unroll
            for (int tt = 0; tt < 8; tt++) {
                if (ks < 2) {
                    MMA16816(cf[tt], aQ[ks], b0[tt], b1[tt]);
                    MMA16816(cf[tt], aQ[ks + 2], b0[tt], b1[tt]);
                } else {
                    MMA16816(cf[tt], aQ[ks - 2], b0[tt], b1[tt]);
                }
            }
        }

        {
            ull mA = *(const ull*)(sp + SM_MB + (wid * 16 + g) * 8);
            ull mB = *(const ull*)(sp + SM_MB + (wid * 16 + g + 8) * 8);
#pragma unroll
            for (int tt = 0; tt < 8; tt++) {
                int j0 = 8 * tt + 2 * tig;
                float p0 = ((mA >> j0) & 1ull)       ? __expf(cf[tt][0]) : 0.f;
                float p1 = ((mA >> (j0 + 1)) & 1ull) ? __expf(cf[tt][1]) : 0.f;
                float p2 = ((mB >> j0) & 1ull)       ? __expf(cf[tt][2]) : 0.f;
                float p3 = ((mB >> (j0 + 1)) & 1ull) ? __expf(cf[tt][3]) : 0.f;
                lsum[0] += p0 + p1;
                lsum[1] += p2 + p3;
                cf[tt][0] = p0; cf[tt][1] = p1;
                cf[tt][2] = p2; cf[tt][3] = p3;
            }
        }

#pragma unroll
        for (int s = 0; s < 4; s++) {
            u32 vh0[4], vh1[4], vl0[4], vl1[4];
#pragma unroll
            for (int tn = 0; tn < 4; tn++) {
                int d = 8 * tn + g;
                int jb = 4 * tig + 32 * s;
                vh0[tn] = *(const u32*)(sp + SM_VB + SWZ(d * 128 + jb));
                vh1[tn] = *(const u32*)(sp + SM_VB + SWZ(d * 128 + jb + 16));
                vl0[tn] = *(const u32*)(sp + SM_VB + SWZ((d + 32) * 128 + jb));
                vl1[tn] = *(const u32*)(sp + SM_VB + SWZ((d + 32) * 128 + jb + 16));
            }
            u32 Ah[4], Al[4];
#pragma unroll
            for (int half = 0; half < 2; half++) {   // C tiles 2s, 2s+1
                const float* c4 = cf[2 * s + half];
                u32 h01 = bf16x2_of(c4[1], c4[0]);
                u32 h23 = bf16x2_of(c4[3], c4[2]);
                Ah[2 * half]     = h01;
                Ah[2 * half + 1] = h23;
                float r0 = __uint_as_float(h01 << 16);
                float r1 = __uint_as_float(h01 & 0xffff0000u);
                float r2 = __uint_as_float(h23 << 16);
                float r3 = __uint_as_float(h23 & 0xffff0000u);
                Al[2 * half]     = bf16x2_of(c4[1] - r1, c4[0] - r0);
                Al[2 * half + 1] = bf16x2_of(c4[3] - r3, c4[2] - r2);
            }
#pragma unroll
            for (int tn = 0; tn < 4; tn++) {
                MMA16816(o[tn], Ah, vh0[tn], vh1[tn]);
                MMA16816(o[tn], Ah, vl0[tn], vl1[tn]);
                MMA16816(o[tn], Al, vh0[tn], vh1[tn]);
            }
        }
        __syncthreads();
    }

#pragma unroll
    for (int r = 0; r < 2; r++) {
        float v = lsum[r];
        v += __shfl_xor_sync(0xffffffffu, v, 1);
        v += __shfl_xor_sync(0xffffffffu, v, 2);
        lsum[r] = v;
    }

    // ---- normalize + write split-bf16 concat-head layout (for out proj) ----
    const int hcol = (bh & 7) * 32;
    {
        int rA = n0 + wid * 16 + g;
        float invA = 1.f / lsum[0];
        float invB = 1.f / lsum[1];
        __nv_bfloat16* baseA = g_attnb + ((size_t)b * NN + rA) * 512 + hcol;
        __nv_bfloat16* baseB = baseA + 8 * 512;
#pragma unroll
        for (int tn = 0; tn < 4; tn++) {
            int dl = 8 * tn + 2 * tig;
            float a0 = o[tn][0] * invA, a1 = o[tn][1] * invA;
            u32 hp = bf16x2_of(a1, a0);
            float r0 = __uint_as_float(hp << 16), r1 = __uint_as_float(hp & 0xffff0000u);
            *(u32*)(baseA + dl) = hp;
            *(u32*)(baseA + 256 + dl) = bf16x2_of(a1 - r1, a0 - r0);
            float b0_ = o[tn][2] * invB, b1_ = o[tn][3] * invB;
            u32 hq = bf16x2_of(b1_, b0_);
            float s0 = __uint_as_float(hq << 16), s1 = __uint_as_float(hq & 0xffff0000u);
            *(u32*)(baseB + dl) = hq;
            *(u32*)(baseB + 256 + dl) = bf16x2_of(b1_ - s1, b0_ - s0);
        }
    }
}

// ---------------- launcher ---------------------------------------------------
extern "C" void kernel_launch(void* const* d_in, const int* in_sizes, int n_in,
                              void* d_out, int out_size) {
    const float* x   = (const float*)d_in[0];
    const float* adj = (const float*)d_in[1];
    const float* Wq  = (const float*)d_in[2];
    const float* Wk  = (const float*)d_in[3];
    const float* Wv  = (const float*)d_in[4];
    const float* Wo  = (const float*)d_in[5];
    const float* bo  = (const float*)d_in[6];
    float* out = (float*)d_out;
    (void)in_sizes; (void)n_in; (void)out_size;

    void *pXb, *pAb;
    cudaGetSymbolAddress(&pXb, g_xb);
    cudaGetSymbolAddress(&pAb, g_attnb);

    adjbits_kernel<<<BB * NN * NWORDS / 256, 256>>>(adj);
    split_x<<<4096 * 64 / 256, 256>>>(x);
    split_w<<<4 * 256 * 64 / 256, 256>>>(Wq, Wk, Wv, Wo);
    hgemm<1><<<dim3(32, 4, 3), 256>>>((const __nv_bfloat16*)pXb, nullptr, nullptr);
    attn_kernel<<<dim3(NN / 128, BH), 256>>>();
    hgemm<0><<<dim3(32, 4), 256>>>((const __nv_bfloat16*)pAb, bo, out);
}